// round 9
// baseline (speedup 1.0000x reference)
#include <cuda_runtime.h>
#include <cuda_fp16.h>

#define Bn 16
#define Cn 1024
#define Tn 2048
#define Dn 512
#define Sn (Tn / 2)
#define EPSf 1e-5f

typedef unsigned int u32;

// ---------------- scratch (static device arrays) ----------------
__device__ __align__(16) __half g_xt [(size_t)Bn * Tn * Cn];        // x^T (B,T,C)
__device__ __align__(16) __half g_wq [Dn * Cn];
__device__ __align__(16) __half g_wkv[2 * Dn * Cn];                 // [Wk; Wv] stacked
__device__ __align__(16) __half g_wo [Cn * Dn];
__device__ __align__(16) __half g_qt [(size_t)Bn * Tn * Dn];        // Q^T (B,T,D)
__device__ __align__(16) __half g_kv [(size_t)Bn * 2 * Dn * Sn];    // [Kp; Vp] pooled (B,2D,S)
__device__ __align__(16) __half g_mt [(size_t)Bn * Dn * Dn];        // Mt = Kp Vp^T
__device__ __align__(16) __half g_p  [(size_t)Bn * Cn * Dn];        // P = Wo M
__device__ __align__(16) __half g_y  [(size_t)Bn * Cn * Tn];        // pre-BN y (fp16)
__device__ float g_bkv[2 * Dn];
__device__ float g_mean[Cn];
__device__ float g_istd[Cn];

// ---------------- PTX helpers ----------------
__device__ __forceinline__ u32 smem_u32(const void* p) {
    u32 a;
    asm("{ .reg .u64 t; cvta.to.shared.u64 t, %1; cvt.u32.u64 %0, t; }" : "=r"(a) : "l"(p));
    return a;
}

#define CPA16(dst, src) \
    asm volatile("cp.async.cg.shared.global [%0], [%1], 16;" :: "r"(dst), "l"(src) : "memory")
#define CP_COMMIT() asm volatile("cp.async.commit_group;" ::: "memory")

#define LDSM4(r, a) \
    asm volatile("ldmatrix.sync.aligned.m8n8.x4.shared.b16 {%0,%1,%2,%3}, [%4];" \
        : "=r"((r)[0]), "=r"((r)[1]), "=r"((r)[2]), "=r"((r)[3]) : "r"(a))

#define MMA_F16(d, a, b0, b1) \
    asm volatile("mma.sync.aligned.m16n8k16.row.col.f32.f16.f16.f32 " \
        "{%0,%1,%2,%3}, {%4,%5,%6,%7}, {%8,%9}, {%0,%1,%2,%3};" \
        : "+f"((d)[0]), "+f"((d)[1]), "+f"((d)[2]), "+f"((d)[3]) \
        : "r"((a)[0]), "r"((a)[1]), "r"((a)[2]), "r"((a)[3]), "r"(b0), "r"(b1))

__device__ __forceinline__ u32 pack_h2(float v0, float v1) {
    __half h0 = __float2half_rn(v0), h1 = __float2half_rn(v1);
    return (u32)__half_as_ushort(h0) | ((u32)__half_as_ushort(h1) << 16);
}

// ---------------- warp-MMA plain-fp16 GEMM, 4-stage pipeline ----------------
// C(M,N) = alpha * A(M,K) * Bt(N,K)^T + bias
// A, Bt row-major K-major fp16; fp32 accumulate. Requires K % 128 == 0.
// BIAS: 0 none, 1 per-row, 2 per-col.
// OMODE: 1 fp16; 3 pool2 along N -> fp16 (N halves).
// CTA 128x128, BK=32, FOUR warps each 64x64 (halves LDSM bytes per MMA:
// smem crossbar was the binder at 32x64 warp tiles), cp.async 4-stage,
// streaming pointers, 80B-padded smem rows (conflict-free ldmatrix).
#define TILE_B 10240           // 128 rows * 80 B
#define BUF_B  (2 * TILE_B)    // A, B
#define SMEM_B (4 * BUF_B)     // 4-stage = 81920

template <int BIAS, int OMODE>
__global__ void __launch_bounds__(128, 2) wgemm(
    const __half* __restrict__ A, const __half* __restrict__ Bt,
    const float* __restrict__ bias,
    __half* __restrict__ Ch,
    int M, int N, int K, float alpha,
    size_t sA, size_t sB, size_t sC)
{
    extern __shared__ __align__(128) char smem[];
    const u32 sbase = smem_u32(smem);
    const int tid = threadIdx.x;
    const int lane = tid & 31;
    const int warp = tid >> 5;      // 0..3
    const int wr = warp >> 1;       // 0..1 -> 64-row block
    const int wc = warp & 1;        // 0..1 -> 64-col block

    A  += (size_t)blockIdx.z * sA;
    Bt += (size_t)blockIdx.z * sB;
    const size_t coff = (size_t)blockIdx.z * sC;

    const int brow = blockIdx.y * 128;
    const int bcol = blockIdx.x * 128;
    const int KT = K >> 5;          // number of BK=32 steps (multiple of 4)

    // ---- streaming load pointers (computed once) ----
    const int rA = tid >> 2;              // 0..31
    const int cA = (tid & 3) * 8;         // 0,8,16,24 halfs
    const __half* pA = A  + (size_t)(brow + rA) * K + cA;
    const __half* pB = Bt + (size_t)(bcol + rA) * K + cA;
    const size_t rskip = (size_t)32 * K;  // next 32-row group
    const u32 dA = sbase + (u32)(rA * 80 + (tid & 3) * 16);
    const u32 dB = dA + TILE_B;

    auto load_at = [&](u32 bufoff, const __half* a, const __half* b) {
#pragma unroll
        for (int it = 0; it < 4; it++) {
            CPA16(dA + bufoff + (u32)it * (32 * 80), a + (size_t)it * rskip);
            CPA16(dB + bufoff + (u32)it * (32 * 80), b + (size_t)it * rskip);
        }
    };

    float acc[4][8][4];
#pragma unroll
    for (int i = 0; i < 4; i++)
#pragma unroll
        for (int j = 0; j < 8; j++)
#pragma unroll
            for (int q = 0; q < 4; q++) acc[i][j][q] = 0.f;

    // ---- 4-stage prologue: load k-tiles 0,1,2 ----
    load_at(0,         pA,      pB);      CP_COMMIT();
    load_at(BUF_B,     pA + 32, pB + 32); CP_COMMIT();
    load_at(2 * BUF_B, pA + 64, pB + 64); CP_COMMIT();
    const __half* qA = pA + 96;
    const __half* qB = pB + 96;

    const u32 rowoff = (u32)(((lane >> 3) & 1) * 8 + (lane & 7));
    const u32 chsel  = (u32)(lane >> 4);
    const u32 aoff = (u32)(wr * 64 + rowoff) * 80 + chsel * 16;
    const u32 boff = TILE_B + (u32)(wc * 64 + rowoff) * 80 + chsel * 16;

    for (int kt0 = 0; kt0 < KT; kt0 += 4) {
#pragma unroll
        for (int u = 0; u < 4; u++) {
            const int kt = kt0 + u;
            asm volatile("cp.async.wait_group 2;" ::: "memory");
            __syncthreads();   // tile kt visible; buffer (kt+3)&3 reusable

            if (kt + 3 < KT) {
                load_at((u32)(((u + 3) & 3)) * BUF_B, qA, qB);
                qA += 32; qB += 32;
            }
            CP_COMMIT();       // commit every iter to keep group counts aligned

            const u32 at = sbase + (u32)u * BUF_B;
#pragma unroll
            for (int ks = 0; ks < 2; ks++) {
                const u32 choff = (u32)ks * 32;
                u32 ar[4][4];
#pragma unroll
                for (int i = 0; i < 4; i++)
                    LDSM4(ar[i], at + aoff + (u32)i * (16 * 80) + choff);
                u32 br[4][4];
#pragma unroll
                for (int j4 = 0; j4 < 4; j4++)
                    LDSM4(br[j4], at + boff + (u32)j4 * (16 * 80) + choff);
#pragma unroll
                for (int i = 0; i < 4; i++)
#pragma unroll
                    for (int j = 0; j < 8; j++) {
                        const int j4 = j >> 1, h = j & 1;
                        MMA_F16(acc[i][j], ar[i], br[j4][h], br[j4][h + 2]);
                    }
            }
        }
    }

    // ---------------- epilogue ----------------
    const int r0 = brow + wr * 64 + (lane >> 2);
    const int c0l = wc * 64 + (lane & 3) * 2;
#pragma unroll
    for (int i = 0; i < 4; i++) {
#pragma unroll
        for (int half = 0; half < 2; half++) {
            const int row = r0 + i * 16 + half * 8;
            const float badd = (BIAS == 1) ? bias[row] : 0.f;
#pragma unroll
            for (int j = 0; j < 8; j++) {
                const int col = bcol + c0l + j * 8;
                float v0 = alpha * acc[i][j][half * 2 + 0] + badd;
                float v1 = alpha * acc[i][j][half * 2 + 1] + badd;
                if (BIAS == 2) { v0 += bias[col]; v1 += bias[col + 1]; }
                if (OMODE == 1) {
                    *(u32*)(Ch + coff + (size_t)row * N + col) = pack_h2(v0, v1);
                } else { // OMODE == 3: maxpool pairs of adjacent cols
                    Ch[coff + (size_t)row * (N >> 1) + (col >> 1)] =
                        __float2half_rn(fmaxf(v0, v1));
                }
            }
        }
    }
}

// ---------------- x (B,C,T) fp32 -> x^T (B,T,C) fp16 ----------------
__global__ void xtrans(const float* __restrict__ x, __half* __restrict__ o)
{
    __shared__ float s[32][33];
    const int b = blockIdx.z;
    const int c0 = blockIdx.y * 32;
    const int t0 = blockIdx.x * 32;
    const int tid = threadIdx.x;
    for (int i = tid; i < 1024; i += 256) {
        const int r = i >> 5, cc = i & 31;
        s[r][cc] = x[((size_t)b * Cn + c0 + r) * Tn + t0 + cc];
    }
    __syncthreads();
    for (int i = tid; i < 512; i += 256) {
        const int r = i >> 4, cp = (i & 15) * 2;
        const size_t oo = ((size_t)b * Tn + t0 + r) * Cn + c0 + cp;
        *(u32*)(o + oo) = pack_h2(s[cp][r], s[cp + 1][r]);
    }
}

// ---------------- 4x weight fp32 -> fp16 (one launch) ----------------
__global__ void wconv4(const float* __restrict__ w0, const float* __restrict__ w1,
                       const float* __restrict__ w2, const float* __restrict__ w3,
                       __half* __restrict__ o0, __half* __restrict__ o1,
                       __half* __restrict__ o2, __half* __restrict__ o3, size_t n4)
{
    const size_t i = (size_t)blockIdx.x * blockDim.x + threadIdx.x;
    if (i >= n4) return;
    const float* srcs[4] = {w0, w1, w2, w3};
    __half* dsts[4] = {o0, o1, o2, o3};
    const float4 v = ((const float4*)srcs[blockIdx.y])[i];
    ((uint2*)dsts[blockIdx.y])[i] = make_uint2(pack_h2(v.x, v.y), pack_h2(v.z, v.w));
}

// ---------------- stack bk|bv into one bias vector ----------------
__global__ void packbias(const float* __restrict__ bk, const float* __restrict__ bv,
                         float* __restrict__ o)
{
    const int i = blockIdx.x * blockDim.x + threadIdx.x;
    if (i < Dn) o[i] = bk[i];
    else if (i < 2 * Dn) o[i] = bv[i - Dn];
}

// ---------------- BN batch stats (fp16 y) ----------------
__global__ void bn_stats(const __half* __restrict__ y,
                         float* __restrict__ mean, float* __restrict__ istd)
{
    const int c = blockIdx.x;
    float s = 0.f, s2 = 0.f;
    for (int b = 0; b < Bn; b++) {
        const __half* row = y + ((size_t)b * Cn + c) * Tn;
        for (int t = threadIdx.x * 8; t < Tn; t += blockDim.x * 8) {
            const uint4 u = *(const uint4*)(row + t);
            const u32 w[4] = {u.x, u.y, u.z, u.w};
#pragma unroll
            for (int q = 0; q < 4; q++) {
                const float2 f = __half22float2(*(const __half2*)&w[q]);
                s  += f.x + f.y;
                s2 += f.x * f.x + f.y * f.y;
            }
        }
    }
#pragma unroll
    for (int o = 16; o > 0; o >>= 1) {
        s  += __shfl_down_sync(0xffffffffu, s,  o);
        s2 += __shfl_down_sync(0xffffffffu, s2, o);
    }
    __shared__ float ss[32], ss2[32];
    const int lane = threadIdx.x & 31, w = threadIdx.x >> 5;
    if (lane == 0) { ss[w] = s; ss2[w] = s2; }
    __syncthreads();
    if (w == 0) {
        const int nw = blockDim.x >> 5;
        s  = lane < nw ? ss[lane]  : 0.f;
        s2 = lane < nw ? ss2[lane] : 0.f;
#pragma unroll
        for (int o = 16; o > 0; o >>= 1) {
            s  += __shfl_down_sync(0xffffffffu, s,  o);
            s2 += __shfl_down_sync(0xffffffffu, s2, o);
        }
        if (lane == 0) {
            const float n = (float)(Bn * Tn);
            const float m = s / n;
            mean[c] = m;
            istd[c] = rsqrtf(s2 / n - m * m + EPSf);
        }
    }
}

// ---------------- BN apply + residual ----------------
__global__ void bn_apply(const __half* __restrict__ y, const float* __restrict__ x,
                         const float* __restrict__ mean, const float* __restrict__ istd,
                         const float* __restrict__ gamma, const float* __restrict__ beta,
                         float* __restrict__ out)
{
    const size_t i4 = ((size_t)blockIdx.x * blockDim.x + threadIdx.x) * 4;
    const size_t total = (size_t)Bn * Cn * Tn;
    if (i4 >= total) return;
    const int c = (int)((i4 / Tn) % Cn);
    const float g = gamma[c] * istd[c];
    const float m = mean[c];
    const float bt = beta[c];
    const uint2 u = *(const uint2*)(y + i4);
    const float2 f0 = __half22float2(*(const __half2*)&u.x);
    const float2 f1 = __half22float2(*(const __half2*)&u.y);
    const float4 xv = *(const float4*)(x + i4);
    float4 o;
    o.x = g * (f0.x - m) + bt + xv.x;
    o.y = g * (f0.y - m) + bt + xv.y;
    o.z = g * (f1.x - m) + bt + xv.z;
    o.w = g * (f1.y - m) + bt + xv.w;
    *(float4*)(out + i4) = o;
}

extern "C" void kernel_launch(void* const* d_in, const int* in_sizes, int n_in,
                              void* d_out, int out_size)
{
    const float* x     = (const float*)d_in[0];
    const float* Wq    = (const float*)d_in[1];
    const float* bq    = (const float*)d_in[2];
    const float* Wk    = (const float*)d_in[3];
    const float* bk    = (const float*)d_in[4];
    const float* Wv    = (const float*)d_in[5];
    const float* bv    = (const float*)d_in[6];
    const float* Wo    = (const float*)d_in[7];
    const float* bo    = (const float*)d_in[8];
    const float* gamma = (const float*)d_in[9];
    const float* beta  = (const float*)d_in[10];
    float* out = (float*)d_out;

    __half *xt, *wq, *wkv, *wo, *qt, *kv, *mt, *pp, *yp;
    float *bkv, *mean, *istd;
    cudaGetSymbolAddress((void**)&xt,  g_xt);
    cudaGetSymbolAddress((void**)&wq,  g_wq);
    cudaGetSymbolAddress((void**)&wkv, g_wkv);
    cudaGetSymbolAddress((void**)&wo,  g_wo);
    cudaGetSymbolAddress((void**)&qt,  g_qt);
    cudaGetSymbolAddress((void**)&kv,  g_kv);
    cudaGetSymbolAddress((void**)&mt,  g_mt);
    cudaGetSymbolAddress((void**)&pp,  g_p);
    cudaGetSymbolAddress((void**)&yp,  g_y);
    cudaGetSymbolAddress((void**)&bkv, g_bkv);
    cudaGetSymbolAddress((void**)&mean, g_mean);
    cudaGetSymbolAddress((void**)&istd, g_istd);

    cudaFuncSetAttribute(wgemm<1, 3>, cudaFuncAttributeMaxDynamicSharedMemorySize, SMEM_B);
    cudaFuncSetAttribute(wgemm<2, 1>, cudaFuncAttributeMaxDynamicSharedMemorySize, SMEM_B);
    cudaFuncSetAttribute(wgemm<0, 1>, cudaFuncAttributeMaxDynamicSharedMemorySize, SMEM_B);
    cudaFuncSetAttribute(wgemm<1, 1>, cudaFuncAttributeMaxDynamicSharedMemorySize, SMEM_B);

    // conversions
    xtrans<<<dim3(Tn / 32, Cn / 32, Bn), 256>>>(x, xt);
    const size_t nw4 = (size_t)Dn * Cn / 4;   // per weight tensor
    wconv4<<<dim3((unsigned)((nw4 + 255) / 256), 4), 256>>>(
        Wk, Wv, Wq, Wo, wkv, wkv + (size_t)Dn * Cn, wq, wo, nw4);
    packbias<<<4, 256>>>(bk, bv, bkv);

    const size_t sTC  = (size_t)Tn * Cn;
    const size_t sTD  = (size_t)Tn * Dn;
    const size_t s2DS = (size_t)2 * Dn * Sn;
    const size_t sDD  = (size_t)Dn * Dn;
    const size_t sCD  = (size_t)Cn * Dn;
    const size_t sCT  = (size_t)Cn * Tn;

    // KV proj + fused pool: [Kp;Vp](2D,S) = pool2(Wkv x + bkv)
    const dim3 gkv(Tn / 128, 2 * Dn / 128, Bn);
    wgemm<1, 3><<<gkv, 128, SMEM_B>>>(wkv, xt, bkv, kv, 2 * Dn, Tn, Cn, 1.f, 0, sTC, s2DS);

    // Q^T(T,D) = xT Wq^T + bq(col)
    const dim3 gq(Dn / 128, Tn / 128, Bn);
    wgemm<2, 1><<<gq, 128, SMEM_B>>>(xt, wq, bq, qt, Tn, Dn, Cn, 1.f, sTC, 0, sTD);

    // Mt(D,D) = Kp Vp^T  (= M^T)
    const dim3 gm(Dn / 128, Dn / 128, Bn);
    wgemm<0, 1><<<gm, 128, SMEM_B>>>(kv, kv + (size_t)Dn * Sn, nullptr, mt,
                                     Dn, Dn, Sn, 1.f, s2DS, s2DS, sDD);

    // P(C,D) = Wo M = Wo Mt^T
    const dim3 gp(Dn / 128, Cn / 128, Bn);
    wgemm<0, 1><<<gp, 128, SMEM_B>>>(wo, mt, nullptr, pp, Cn, Dn, Dn, 1.f, 0, sDD, sCD);

    // y(C,T) = (1/T) P Q + bo
    const dim3 gy(Tn / 128, Cn / 128, Bn);
    wgemm<1, 1><<<gy, 128, SMEM_B>>>(pp, qt, bo, yp, Cn, Tn, Dn, 1.f / (float)Tn,
                                     sCD, sTD, sCT);

    // BatchNorm + residual
    bn_stats<<<Cn, 256>>>(yp, mean, istd);
    const size_t total4 = (size_t)Bn * Cn * Tn / 4;
    bn_apply<<<(unsigned)((total4 + 255) / 256), 256>>>(yp, x, mean, istd, gamma, beta, out);
}

// round 11
// speedup vs baseline: 1.0918x; 1.0918x over previous
#include <cuda_runtime.h>
#include <cuda_fp16.h>

#define Bn 16
#define Cn 1024
#define Tn 2048
#define Dn 512
#define Sn (Tn / 2)
#define EPSf 1e-5f

typedef unsigned int u32;

// ---------------- scratch (static device arrays) ----------------
__device__ __align__(16) __half g_xt [(size_t)Bn * Tn * Cn];        // x^T (B,T,C)
__device__ __align__(16) __half g_wq [Dn * Cn];
__device__ __align__(16) __half g_wkv[2 * Dn * Cn];                 // [Wk; Wv] stacked
__device__ __align__(16) __half g_wo [Cn * Dn];
__device__ __align__(16) __half g_qt [(size_t)Bn * Tn * Dn];        // Q^T (B,T,D)
__device__ __align__(16) __half g_kv [(size_t)Bn * 2 * Dn * Sn];    // [Kp; Vp] pooled (B,2D,S)
__device__ __align__(16) __half g_mt [(size_t)Bn * Dn * Dn];        // Mt = Kp Vp^T
__device__ __align__(16) __half g_p  [(size_t)Bn * Cn * Dn];        // P = Wo M
__device__ __align__(16) __half g_y  [(size_t)Bn * Cn * Tn];        // pre-BN y (fp16)
__device__ float g_bkv[2 * Dn];
__device__ float g_mean[Cn];
__device__ float g_istd[Cn];

// ---------------- PTX helpers ----------------
__device__ __forceinline__ u32 smem_u32(const void* p) {
    u32 a;
    asm("{ .reg .u64 t; cvta.to.shared.u64 t, %1; cvt.u32.u64 %0, t; }" : "=r"(a) : "l"(p));
    return a;
}

#define CPA16(dst, src) \
    asm volatile("cp.async.cg.shared.global [%0], [%1], 16;" :: "r"(dst), "l"(src) : "memory")
#define CP_COMMIT() asm volatile("cp.async.commit_group;" ::: "memory")

#define LDSM4(r, a) \
    asm volatile("ldmatrix.sync.aligned.m8n8.x4.shared.b16 {%0,%1,%2,%3}, [%4];" \
        : "=r"((r)[0]), "=r"((r)[1]), "=r"((r)[2]), "=r"((r)[3]) : "r"(a))

#define MMA_F16(d, a, b0, b1) \
    asm volatile("mma.sync.aligned.m16n8k16.row.col.f32.f16.f16.f32 " \
        "{%0,%1,%2,%3}, {%4,%5,%6,%7}, {%8,%9}, {%0,%1,%2,%3};" \
        : "+f"((d)[0]), "+f"((d)[1]), "+f"((d)[2]), "+f"((d)[3]) \
        : "r"((a)[0]), "r"((a)[1]), "r"((a)[2]), "r"((a)[3]), "r"(b0), "r"(b1))

__device__ __forceinline__ u32 pack_h2(float v0, float v1) {
    __half h0 = __float2half_rn(v0), h1 = __float2half_rn(v1);
    return (u32)__half_as_ushort(h0) | ((u32)__half_as_ushort(h1) << 16);
}

// ---------------- warp-MMA plain-fp16 GEMM ----------------
// C(M,N) = alpha * A(M,K) * Bt(N,K)^T + bias
// A, Bt row-major K-major fp16; fp32 accumulate. Requires K % 128 == 0.
// BIAS: 0 none, 1 per-row, 2 per-col.
// OMODE: 1 fp16; 3 pool2 along N -> fp16 (N halves).
// Round-8 shape (CTA 128x128, 8 warps of 32x64, 256 thr, 2 CTA/SM),
// BK=64 per stage, 3-stage ring, ONE commit per iter.
// PIPELINE INVARIANT: prologue commits 2 groups; at iter kt the pending
// set is {kt, kt+1}; cp.async.wait_group 1 drains to <=1 pending, which
// guarantees tile kt's group is complete. (wait_group 2 here was the
// round-10 NaN: at kt=0 it was a no-op over the 2 pending groups.)
// 144B-padded rows (conflict-free ldmatrix).
#define TILE_B 18432           // 128 rows * 144 B
#define BUF_B  (2 * TILE_B)    // A, B
#define SMEM_B (3 * BUF_B)     // 3-stage = 110592 (2 CTAs = 216 KB)

template <int BIAS, int OMODE>
__global__ void __launch_bounds__(256, 2) wgemm(
    const __half* __restrict__ A, const __half* __restrict__ Bt,
    const float* __restrict__ bias,
    __half* __restrict__ Ch,
    int M, int N, int K, float alpha,
    size_t sA, size_t sB, size_t sC)
{
    extern __shared__ __align__(128) char smem[];
    const u32 sbase = smem_u32(smem);
    const int tid = threadIdx.x;
    const int lane = tid & 31;
    const int warp = tid >> 5;
    const int wr = warp >> 1;       // 0..3 -> 32-row block
    const int wc = warp & 1;        // 0..1 -> 64-col block

    A  += (size_t)blockIdx.z * sA;
    Bt += (size_t)blockIdx.z * sB;
    const size_t coff = (size_t)blockIdx.z * sC;

    const int brow = blockIdx.y * 128;
    const int bcol = blockIdx.x * 128;
    const int KT = K >> 6;          // number of BK=64 steps

    // ---- streaming load pointers (computed once) ----
    const int rA = tid >> 3;              // 0..31
    const int cA = (tid & 7) * 8;         // 0..56 halfs (16B chunks)
    const __half* pA = A  + (size_t)(brow + rA) * K + cA;
    const __half* pB = Bt + (size_t)(bcol + rA) * K + cA;
    const size_t rskip = (size_t)32 * K;  // next 32-row group
    const u32 dA = sbase + (u32)(rA * 144 + (tid & 7) * 16);
    const u32 dB = dA + TILE_B;

    auto load_at = [&](u32 bufoff, const __half* a, const __half* b) {
#pragma unroll
        for (int it = 0; it < 4; it++) {
            CPA16(dA + bufoff + (u32)it * (32 * 144), a + (size_t)it * rskip);
            CPA16(dB + bufoff + (u32)it * (32 * 144), b + (size_t)it * rskip);
        }
    };

    float acc[2][8][4];
#pragma unroll
    for (int i = 0; i < 2; i++)
#pragma unroll
        for (int j = 0; j < 8; j++)
#pragma unroll
            for (int q = 0; q < 4; q++) acc[i][j][q] = 0.f;

    // ---- 3-stage prologue: load k-tiles 0,1 (2 committed groups) ----
    load_at(0,     pA,      pB);      CP_COMMIT();
    load_at(BUF_B, pA + 64, pB + 64); CP_COMMIT();
    const __half* qA = pA + 128;
    const __half* qB = pB + 128;

    const u32 rowoff = (u32)(((lane >> 3) & 1) * 8 + (lane & 7));
    const u32 chsel  = (u32)(lane >> 4);
    const u32 aoff = (u32)(wr * 32 + rowoff) * 144 + chsel * 16;
    const u32 boff = TILE_B + (u32)(wc * 64 + rowoff) * 144 + chsel * 16;

    int buf = 0;
    for (int kt = 0; kt < KT; kt++) {
        asm volatile("cp.async.wait_group 1;" ::: "memory");
        __syncthreads();   // tile kt visible; next write buffer reusable

        if (kt + 2 < KT) {
            int nb = buf + 2; if (nb >= 3) nb -= 3;
            load_at((u32)nb * BUF_B, qA, qB);
            qA += 64; qB += 64;
        }
        CP_COMMIT();       // one group per iter (possibly empty at tail)

        const u32 at = sbase + (u32)buf * BUF_B;
#pragma unroll
        for (int ks = 0; ks < 4; ks++) {
            const u32 choff = (u32)ks * 32;
            u32 ar[2][4];
#pragma unroll
            for (int i = 0; i < 2; i++)
                LDSM4(ar[i], at + aoff + (u32)i * (16 * 144) + choff);
            u32 br[4][4];
#pragma unroll
            for (int j4 = 0; j4 < 4; j4++)
                LDSM4(br[j4], at + boff + (u32)j4 * (16 * 144) + choff);
#pragma unroll
            for (int i = 0; i < 2; i++)
#pragma unroll
                for (int j = 0; j < 8; j++) {
                    const int j4 = j >> 1, h = j & 1;
                    MMA_F16(acc[i][j], ar[i], br[j4][h], br[j4][h + 2]);
                }
        }
        if (++buf == 3) buf = 0;
    }

    // ---------------- epilogue ----------------
    const int r0 = brow + wr * 32 + (lane >> 2);
    const int c0l = wc * 64 + (lane & 3) * 2;
#pragma unroll
    for (int i = 0; i < 2; i++) {
#pragma unroll
        for (int half = 0; half < 2; half++) {
            const int row = r0 + i * 16 + half * 8;
            const float badd = (BIAS == 1) ? bias[row] : 0.f;
#pragma unroll
            for (int j = 0; j < 8; j++) {
                const int col = bcol + c0l + j * 8;
                float v0 = alpha * acc[i][j][half * 2 + 0] + badd;
                float v1 = alpha * acc[i][j][half * 2 + 1] + badd;
                if (BIAS == 2) { v0 += bias[col]; v1 += bias[col + 1]; }
                if (OMODE == 1) {
                    *(u32*)(Ch + coff + (size_t)row * N + col) = pack_h2(v0, v1);
                } else { // OMODE == 3: maxpool pairs of adjacent cols
                    Ch[coff + (size_t)row * (N >> 1) + (col >> 1)] =
                        __float2half_rn(fmaxf(v0, v1));
                }
            }
        }
    }
}

// ---------------- x (B,C,T) fp32 -> x^T (B,T,C) fp16 ----------------
__global__ void xtrans(const float* __restrict__ x, __half* __restrict__ o)
{
    __shared__ float s[32][33];
    const int b = blockIdx.z;
    const int c0 = blockIdx.y * 32;
    const int t0 = blockIdx.x * 32;
    const int tid = threadIdx.x;
    for (int i = tid; i < 1024; i += 256) {
        const int r = i >> 5, cc = i & 31;
        s[r][cc] = x[((size_t)b * Cn + c0 + r) * Tn + t0 + cc];
    }
    __syncthreads();
    for (int i = tid; i < 512; i += 256) {
        const int r = i >> 4, cp = (i & 15) * 2;
        const size_t oo = ((size_t)b * Tn + t0 + r) * Cn + c0 + cp;
        *(u32*)(o + oo) = pack_h2(s[cp][r], s[cp + 1][r]);
    }
}

// ---------------- 4x weight fp32 -> fp16 (one launch) ----------------
__global__ void wconv4(const float* __restrict__ w0, const float* __restrict__ w1,
                       const float* __restrict__ w2, const float* __restrict__ w3,
                       __half* __restrict__ o0, __half* __restrict__ o1,
                       __half* __restrict__ o2, __half* __restrict__ o3, size_t n4)
{
    const size_t i = (size_t)blockIdx.x * blockDim.x + threadIdx.x;
    if (i >= n4) return;
    const float* srcs[4] = {w0, w1, w2, w3};
    __half* dsts[4] = {o0, o1, o2, o3};
    const float4 v = ((const float4*)srcs[blockIdx.y])[i];
    ((uint2*)dsts[blockIdx.y])[i] = make_uint2(pack_h2(v.x, v.y), pack_h2(v.z, v.w));
}

// ---------------- stack bk|bv into one bias vector ----------------
__global__ void packbias(const float* __restrict__ bk, const float* __restrict__ bv,
                         float* __restrict__ o)
{
    const int i = blockIdx.x * blockDim.x + threadIdx.x;
    if (i < Dn) o[i] = bk[i];
    else if (i < 2 * Dn) o[i] = bv[i - Dn];
}

// ---------------- BN batch stats (fp16 y) ----------------
__global__ void bn_stats(const __half* __restrict__ y,
                         float* __restrict__ mean, float* __restrict__ istd)
{
    const int c = blockIdx.x;
    float s = 0.f, s2 = 0.f;
    for (int b = 0; b < Bn; b++) {
        const __half* row = y + ((size_t)b * Cn + c) * Tn;
        for (int t = threadIdx.x * 8; t < Tn; t += blockDim.x * 8) {
            const uint4 u = *(const uint4*)(row + t);
            const u32 w[4] = {u.x, u.y, u.z, u.w};
#pragma unroll
            for (int q = 0; q < 4; q++) {
                const float2 f = __half22float2(*(const __half2*)&w[q]);
                s  += f.x + f.y;
                s2 += f.x * f.x + f.y * f.y;
            }
        }
    }
#pragma unroll
    for (int o = 16; o > 0; o >>= 1) {
        s  += __shfl_down_sync(0xffffffffu, s,  o);
        s2 += __shfl_down_sync(0xffffffffu, s2, o);
    }
    __shared__ float ss[32], ss2[32];
    const int lane = threadIdx.x & 31, w = threadIdx.x >> 5;
    if (lane == 0) { ss[w] = s; ss2[w] = s2; }
    __syncthreads();
    if (w == 0) {
        const int nw = blockDim.x >> 5;
        s  = lane < nw ? ss[lane]  : 0.f;
        s2 = lane < nw ? ss2[lane] : 0.f;
#pragma unroll
        for (int o = 16; o > 0; o >>= 1) {
            s  += __shfl_down_sync(0xffffffffu, s,  o);
            s2 += __shfl_down_sync(0xffffffffu, s2, o);
        }
        if (lane == 0) {
            const float n = (float)(Bn * Tn);
            const float m = s / n;
            mean[c] = m;
            istd[c] = rsqrtf(s2 / n - m * m + EPSf);
        }
    }
}

// ---------------- BN apply + residual ----------------
__global__ void bn_apply(const __half* __restrict__ y, const float* __restrict__ x,
                         const float* __restrict__ mean, const float* __restrict__ istd,
                         const float* __restrict__ gamma, const float* __restrict__ beta,
                         float* __restrict__ out)
{
    const size_t i4 = ((size_t)blockIdx.x * blockDim.x + threadIdx.x) * 4;
    const size_t total = (size_t)Bn * Cn * Tn;
    if (i4 >= total) return;
    const int c = (int)((i4 / Tn) % Cn);
    const float g = gamma[c] * istd[c];
    const float m = mean[c];
    const float bt = beta[c];
    const uint2 u = *(const uint2*)(y + i4);
    const float2 f0 = __half22float2(*(const __half2*)&u.x);
    const float2 f1 = __half22float2(*(const __half2*)&u.y);
    const float4 xv = *(const float4*)(x + i4);
    float4 o;
    o.x = g * (f0.x - m) + bt + xv.x;
    o.y = g * (f0.y - m) + bt + xv.y;
    o.z = g * (f1.x - m) + bt + xv.z;
    o.w = g * (f1.y - m) + bt + xv.w;
    *(float4*)(out + i4) = o;
}

extern "C" void kernel_launch(void* const* d_in, const int* in_sizes, int n_in,
                              void* d_out, int out_size)
{
    const float* x     = (const float*)d_in[0];
    const float* Wq    = (const float*)d_in[1];
    const float* bq    = (const float*)d_in[2];
    const float* Wk    = (const float*)d_in[3];
    const float* bk    = (const float*)d_in[4];
    const float* Wv    = (const float*)d_in[5];
    const float* bv    = (const float*)d_in[6];
    const float* Wo    = (const float*)d_in[7];
    const float* bo    = (const float*)d_in[8];
    const float* gamma = (const float*)d_in[9];
    const float* beta  = (const float*)d_in[10];
    float* out = (float*)d_out;

    __half *xt, *wq, *wkv, *wo, *qt, *kv, *mt, *pp, *yp;
    float *bkv, *mean, *istd;
    cudaGetSymbolAddress((void**)&xt,  g_xt);
    cudaGetSymbolAddress((void**)&wq,  g_wq);
    cudaGetSymbolAddress((void**)&wkv, g_wkv);
    cudaGetSymbolAddress((void**)&wo,  g_wo);
    cudaGetSymbolAddress((void**)&qt,  g_qt);
    cudaGetSymbolAddress((void**)&kv,  g_kv);
    cudaGetSymbolAddress((void**)&mt,  g_mt);
    cudaGetSymbolAddress((void**)&pp,  g_p);
    cudaGetSymbolAddress((void**)&yp,  g_y);
    cudaGetSymbolAddress((void**)&bkv, g_bkv);
    cudaGetSymbolAddress((void**)&mean, g_mean);
    cudaGetSymbolAddress((void**)&istd, g_istd);

    cudaFuncSetAttribute(wgemm<1, 3>, cudaFuncAttributeMaxDynamicSharedMemorySize, SMEM_B);
    cudaFuncSetAttribute(wgemm<2, 1>, cudaFuncAttributeMaxDynamicSharedMemorySize, SMEM_B);
    cudaFuncSetAttribute(wgemm<0, 1>, cudaFuncAttributeMaxDynamicSharedMemorySize, SMEM_B);
    cudaFuncSetAttribute(wgemm<1, 1>, cudaFuncAttributeMaxDynamicSharedMemorySize, SMEM_B);

    // conversions
    xtrans<<<dim3(Tn / 32, Cn / 32, Bn), 256>>>(x, xt);
    const size_t nw4 = (size_t)Dn * Cn / 4;   // per weight tensor
    wconv4<<<dim3((unsigned)((nw4 + 255) / 256), 4), 256>>>(
        Wk, Wv, Wq, Wo, wkv, wkv + (size_t)Dn * Cn, wq, wo, nw4);
    packbias<<<4, 256>>>(bk, bv, bkv);

    const size_t sTC  = (size_t)Tn * Cn;
    const size_t sTD  = (size_t)Tn * Dn;
    const size_t s2DS = (size_t)2 * Dn * Sn;
    const size_t sDD  = (size_t)Dn * Dn;
    const size_t sCD  = (size_t)Cn * Dn;
    const size_t sCT  = (size_t)Cn * Tn;

    // KV proj + fused pool: [Kp;Vp](2D,S) = pool2(Wkv x + bkv)
    const dim3 gkv(Tn / 128, 2 * Dn / 128, Bn);
    wgemm<1, 3><<<gkv, 256, SMEM_B>>>(wkv, xt, bkv, kv, 2 * Dn, Tn, Cn, 1.f, 0, sTC, s2DS);

    // Q^T(T,D) = xT Wq^T + bq(col)
    const dim3 gq(Dn / 128, Tn / 128, Bn);
    wgemm<2, 1><<<gq, 256, SMEM_B>>>(xt, wq, bq, qt, Tn, Dn, Cn, 1.f, sTC, 0, sTD);

    // Mt(D,D) = Kp Vp^T  (= M^T)
    const dim3 gm(Dn / 128, Dn / 128, Bn);
    wgemm<0, 1><<<gm, 256, SMEM_B>>>(kv, kv + (size_t)Dn * Sn, nullptr, mt,
                                     Dn, Dn, Sn, 1.f, s2DS, s2DS, sDD);

    // P(C,D) = Wo M = Wo Mt^T
    const dim3 gp(Dn / 128, Cn / 128, Bn);
    wgemm<0, 1><<<gp, 256, SMEM_B>>>(wo, mt, nullptr, pp, Cn, Dn, Dn, 1.f, 0, sDD, sCD);

    // y(C,T) = (1/T) P Q + bo
    const dim3 gy(Tn / 128, Cn / 128, Bn);
    wgemm<1, 1><<<gy, 256, SMEM_B>>>(pp, qt, bo, yp, Cn, Tn, Dn, 1.f / (float)Tn,
                                     sCD, sTD, sCT);

    // BatchNorm + residual
    bn_stats<<<Cn, 256>>>(yp, mean, istd);
    const size_t total4 = (size_t)Bn * Cn * Tn / 4;
    bn_apply<<<(unsigned)((total4 + 255) / 256), 256>>>(yp, x, mean, istd, gamma, beta, out);
}

// round 12
// speedup vs baseline: 1.1071x; 1.0140x over previous
#include <cuda_runtime.h>
#include <cuda_fp16.h>

#define Bn 16
#define Cn 1024
#define Tn 2048
#define Dn 512
#define Sn (Tn / 2)
#define EPSf 1e-5f

typedef unsigned int u32;

// ---------------- scratch (static device arrays) ----------------
__device__ __align__(16) __half g_xt [(size_t)Bn * Tn * Cn];        // x^T (B,T,C)
__device__ __align__(16) __half g_wq [Dn * Cn];
__device__ __align__(16) __half g_wkv[2 * Dn * Cn];                 // [Wk; Wv] stacked
__device__ __align__(16) __half g_wo [Cn * Dn];
__device__ __align__(16) __half g_qt [(size_t)Bn * Tn * Dn];        // Q^T (B,T,D)
__device__ __align__(16) __half g_kv [(size_t)Bn * 2 * Dn * Sn];    // [Kp; Vp] pooled (B,2D,S)
__device__ __align__(16) __half g_mt [(size_t)Bn * Dn * Dn];        // Mt = Kp Vp^T
__device__ __align__(16) __half g_p  [(size_t)Bn * Cn * Dn];        // P = Wo M
__device__ __align__(16) __half g_y  [(size_t)Bn * Cn * Tn];        // pre-BN y (fp16)
__device__ float g_bkv[2 * Dn];
__device__ float g_mean[Cn];
__device__ float g_istd[Cn];

// ---------------- PTX helpers ----------------
__device__ __forceinline__ u32 smem_u32(const void* p) {
    u32 a;
    asm("{ .reg .u64 t; cvta.to.shared.u64 t, %1; cvt.u32.u64 %0, t; }" : "=r"(a) : "l"(p));
    return a;
}

#define CPA16(dst, src) \
    asm volatile("cp.async.cg.shared.global [%0], [%1], 16;" :: "r"(dst), "l"(src) : "memory")
#define CP_COMMIT() asm volatile("cp.async.commit_group;" ::: "memory")

#define LDSM4(r, a) \
    asm volatile("ldmatrix.sync.aligned.m8n8.x4.shared.b16 {%0,%1,%2,%3}, [%4];" \
        : "=r"((r)[0]), "=r"((r)[1]), "=r"((r)[2]), "=r"((r)[3]) : "r"(a))

#define MMA_F16(d, a, b0, b1) \
    asm volatile("mma.sync.aligned.m16n8k16.row.col.f32.f16.f16.f32 " \
        "{%0,%1,%2,%3}, {%4,%5,%6,%7}, {%8,%9}, {%0,%1,%2,%3};" \
        : "+f"((d)[0]), "+f"((d)[1]), "+f"((d)[2]), "+f"((d)[3]) \
        : "r"((a)[0]), "r"((a)[1]), "r"((a)[2]), "r"((a)[3]), "r"(b0), "r"(b1))

__device__ __forceinline__ u32 pack_h2(float v0, float v1) {
    __half h0 = __float2half_rn(v0), h1 = __float2half_rn(v1);
    return (u32)__half_as_ushort(h0) | ((u32)__half_as_ushort(h1) << 16);
}

// ---------------- warp-MMA plain-fp16 GEMM ----------------
// C(M,N) = alpha * A(M,K) * Bt(N,K)^T + bias
// A, Bt row-major K-major fp16; fp32 accumulate. Requires K % 128 == 0.
// BIAS: 0 none, 1 per-row, 2 per-col.
// OMODE: 1 fp16; 3 pool2 along N -> fp16 (N halves).
// CTA 128x128, 8 warps of 32x64, 256 thr, 2 CTA/SM; BK=64, 3-stage ring
// (prologue commits 2 groups; wait_group 1 at iter kt guarantees tile kt).
// NEW: fragment software pipelining — B frags double-buffered across the 4
// k16 substeps, next-A LDSM issued after each MMA burst, so LDSM (crossbar)
// and MMA (tensor) run CONCURRENTLY instead of phase-locked bursts
// (both pipes were ~50%, each near its standalone saturation).
// 144B-padded rows (conflict-free ldmatrix).
#define TILE_B 18432           // 128 rows * 144 B
#define BUF_B  (2 * TILE_B)    // A, B
#define SMEM_B (3 * BUF_B)     // 3-stage = 110592 (2 CTAs = 216 KB)

template <int BIAS, int OMODE>
__global__ void __launch_bounds__(256, 2) wgemm(
    const __half* __restrict__ A, const __half* __restrict__ Bt,
    const float* __restrict__ bias,
    __half* __restrict__ Ch,
    int M, int N, int K, float alpha,
    size_t sA, size_t sB, size_t sC)
{
    extern __shared__ __align__(128) char smem[];
    const u32 sbase = smem_u32(smem);
    const int tid = threadIdx.x;
    const int lane = tid & 31;
    const int warp = tid >> 5;
    const int wr = warp >> 1;       // 0..3 -> 32-row block
    const int wc = warp & 1;        // 0..1 -> 64-col block

    A  += (size_t)blockIdx.z * sA;
    Bt += (size_t)blockIdx.z * sB;
    const size_t coff = (size_t)blockIdx.z * sC;

    const int brow = blockIdx.y * 128;
    const int bcol = blockIdx.x * 128;
    const int KT = K >> 6;          // number of BK=64 steps

    // ---- streaming load pointers (computed once) ----
    const int rA = tid >> 3;              // 0..31
    const int cA = (tid & 7) * 8;         // 0..56 halfs (16B chunks)
    const __half* pA = A  + (size_t)(brow + rA) * K + cA;
    const __half* pB = Bt + (size_t)(bcol + rA) * K + cA;
    const size_t rskip = (size_t)32 * K;  // next 32-row group
    const u32 dA = sbase + (u32)(rA * 144 + (tid & 7) * 16);
    const u32 dB = dA + TILE_B;

    auto load_at = [&](u32 bufoff, const __half* a, const __half* b) {
#pragma unroll
        for (int it = 0; it < 4; it++) {
            CPA16(dA + bufoff + (u32)it * (32 * 144), a + (size_t)it * rskip);
            CPA16(dB + bufoff + (u32)it * (32 * 144), b + (size_t)it * rskip);
        }
    };

    float acc[2][8][4];
#pragma unroll
    for (int i = 0; i < 2; i++)
#pragma unroll
        for (int j = 0; j < 8; j++)
#pragma unroll
            for (int q = 0; q < 4; q++) acc[i][j][q] = 0.f;

    // ---- 3-stage prologue: load k-tiles 0,1 (2 committed groups) ----
    load_at(0,     pA,      pB);      CP_COMMIT();
    load_at(BUF_B, pA + 64, pB + 64); CP_COMMIT();
    const __half* qA = pA + 128;
    const __half* qB = pB + 128;

    const u32 rowoff = (u32)(((lane >> 3) & 1) * 8 + (lane & 7));
    const u32 chsel  = (u32)(lane >> 4);
    const u32 aoff = (u32)(wr * 32 + rowoff) * 144 + chsel * 16;
    const u32 boff = TILE_B + (u32)(wc * 64 + rowoff) * 144 + chsel * 16;

    int buf = 0;
    for (int kt = 0; kt < KT; kt++) {
        asm volatile("cp.async.wait_group 1;" ::: "memory");
        __syncthreads();   // tile kt visible; next write buffer reusable

        if (kt + 2 < KT) {
            int nb = buf + 2; if (nb >= 3) nb -= 3;
            load_at((u32)nb * BUF_B, qA, qB);
            qA += 64; qB += 64;
        }
        CP_COMMIT();       // one group per iter (possibly empty at tail)

        const u32 at = sbase + (u32)buf * BUF_B;
        const u32 abase = at + aoff;
        const u32 bbase = at + boff;

        // ---- fragment-pipelined 4x k16 substeps ----
        u32 ar[2][4];        // A frags, single buffer (reloaded post-MMA)
        u32 br[2][4][4];     // B frags, double buffer
#pragma unroll
        for (int j4 = 0; j4 < 4; j4++)
            LDSM4(br[0][j4], bbase + (u32)j4 * (16 * 144));
#pragma unroll
        for (int i = 0; i < 2; i++)
            LDSM4(ar[i], abase + (u32)i * (16 * 144));

#pragma unroll
        for (int ks = 0; ks < 4; ks++) {
            const int cur = ks & 1;
            const int nxt = cur ^ 1;
            const u32 nchoff = (u32)(ks + 1) * 32;
            if (ks < 3) {   // prefetch next-substep B while MMAs run
#pragma unroll
                for (int j4 = 0; j4 < 4; j4++)
                    LDSM4(br[nxt][j4], bbase + (u32)j4 * (16 * 144) + nchoff);
            }
#pragma unroll
            for (int i = 0; i < 2; i++)
#pragma unroll
                for (int j = 0; j < 8; j++) {
                    const int j4 = j >> 1, h = j & 1;
                    MMA_F16(acc[i][j], ar[i], br[cur][j4][h], br[cur][j4][h + 2]);
                }
            if (ks < 3) {   // reload A for next substep after its last use
#pragma unroll
                for (int i = 0; i < 2; i++)
                    LDSM4(ar[i], abase + (u32)i * (16 * 144) + nchoff);
            }
        }
        if (++buf == 3) buf = 0;
    }

    // ---------------- epilogue ----------------
    const int r0 = brow + wr * 32 + (lane >> 2);
    const int c0l = wc * 64 + (lane & 3) * 2;
#pragma unroll
    for (int i = 0; i < 2; i++) {
#pragma unroll
        for (int half = 0; half < 2; half++) {
            const int row = r0 + i * 16 + half * 8;
            const float badd = (BIAS == 1) ? bias[row] : 0.f;
#pragma unroll
            for (int j = 0; j < 8; j++) {
                const int col = bcol + c0l + j * 8;
                float v0 = alpha * acc[i][j][half * 2 + 0] + badd;
                float v1 = alpha * acc[i][j][half * 2 + 1] + badd;
                if (BIAS == 2) { v0 += bias[col]; v1 += bias[col + 1]; }
                if (OMODE == 1) {
                    *(u32*)(Ch + coff + (size_t)row * N + col) = pack_h2(v0, v1);
                } else { // OMODE == 3: maxpool pairs of adjacent cols
                    Ch[coff + (size_t)row * (N >> 1) + (col >> 1)] =
                        __float2half_rn(fmaxf(v0, v1));
                }
            }
        }
    }
}

// ---------------- x (B,C,T) fp32 -> x^T (B,T,C) fp16 ----------------
__global__ void xtrans(const float* __restrict__ x, __half* __restrict__ o)
{
    __shared__ float s[32][33];
    const int b = blockIdx.z;
    const int c0 = blockIdx.y * 32;
    const int t0 = blockIdx.x * 32;
    const int tid = threadIdx.x;
    for (int i = tid; i < 1024; i += 256) {
        const int r = i >> 5, cc = i & 31;
        s[r][cc] = x[((size_t)b * Cn + c0 + r) * Tn + t0 + cc];
    }
    __syncthreads();
    for (int i = tid; i < 512; i += 256) {
        const int r = i >> 4, cp = (i & 15) * 2;
        const size_t oo = ((size_t)b * Tn + t0 + r) * Cn + c0 + cp;
        *(u32*)(o + oo) = pack_h2(s[cp][r], s[cp + 1][r]);
    }
}

// ---------------- 4x weight fp32 -> fp16 (one launch) ----------------
__global__ void wconv4(const float* __restrict__ w0, const float* __restrict__ w1,
                       const float* __restrict__ w2, const float* __restrict__ w3,
                       __half* __restrict__ o0, __half* __restrict__ o1,
                       __half* __restrict__ o2, __half* __restrict__ o3, size_t n4)
{
    const size_t i = (size_t)blockIdx.x * blockDim.x + threadIdx.x;
    if (i >= n4) return;
    const float* srcs[4] = {w0, w1, w2, w3};
    __half* dsts[4] = {o0, o1, o2, o3};
    const float4 v = ((const float4*)srcs[blockIdx.y])[i];
    ((uint2*)dsts[blockIdx.y])[i] = make_uint2(pack_h2(v.x, v.y), pack_h2(v.z, v.w));
}

// ---------------- stack bk|bv into one bias vector ----------------
__global__ void packbias(const float* __restrict__ bk, const float* __restrict__ bv,
                         float* __restrict__ o)
{
    const int i = blockIdx.x * blockDim.x + threadIdx.x;
    if (i < Dn) o[i] = bk[i];
    else if (i < 2 * Dn) o[i] = bv[i - Dn];
}

// ---------------- BN batch stats (fp16 y) ----------------
__global__ void bn_stats(const __half* __restrict__ y,
                         float* __restrict__ mean, float* __restrict__ istd)
{
    const int c = blockIdx.x;
    float s = 0.f, s2 = 0.f;
    for (int b = 0; b < Bn; b++) {
        const __half* row = y + ((size_t)b * Cn + c) * Tn;
        for (int t = threadIdx.x * 8; t < Tn; t += blockDim.x * 8) {
            const uint4 u = *(const uint4*)(row + t);
            const u32 w[4] = {u.x, u.y, u.z, u.w};
#pragma unroll
            for (int q = 0; q < 4; q++) {
                const float2 f = __half22float2(*(const __half2*)&w[q]);
                s  += f.x + f.y;
                s2 += f.x * f.x + f.y * f.y;
            }
        }
    }
#pragma unroll
    for (int o = 16; o > 0; o >>= 1) {
        s  += __shfl_down_sync(0xffffffffu, s,  o);
        s2 += __shfl_down_sync(0xffffffffu, s2, o);
    }
    __shared__ float ss[32], ss2[32];
    const int lane = threadIdx.x & 31, w = threadIdx.x >> 5;
    if (lane == 0) { ss[w] = s; ss2[w] = s2; }
    __syncthreads();
    if (w == 0) {
        const int nw = blockDim.x >> 5;
        s  = lane < nw ? ss[lane]  : 0.f;
        s2 = lane < nw ? ss2[lane] : 0.f;
#pragma unroll
        for (int o = 16; o > 0; o >>= 1) {
            s  += __shfl_down_sync(0xffffffffu, s,  o);
            s2 += __shfl_down_sync(0xffffffffu, s2, o);
        }
        if (lane == 0) {
            const float n = (float)(Bn * Tn);
            const float m = s / n;
            mean[c] = m;
            istd[c] = rsqrtf(s2 / n - m * m + EPSf);
        }
    }
}

// ---------------- BN apply + residual ----------------
__global__ void bn_apply(const __half* __restrict__ y, const float* __restrict__ x,
                         const float* __restrict__ mean, const float* __restrict__ istd,
                         const float* __restrict__ gamma, const float* __restrict__ beta,
                         float* __restrict__ out)
{
    const size_t i4 = ((size_t)blockIdx.x * blockDim.x + threadIdx.x) * 4;
    const size_t total = (size_t)Bn * Cn * Tn;
    if (i4 >= total) return;
    const int c = (int)((i4 / Tn) % Cn);
    const float g = gamma[c] * istd[c];
    const float m = mean[c];
    const float bt = beta[c];
    const uint2 u = *(const uint2*)(y + i4);
    const float2 f0 = __half22float2(*(const __half2*)&u.x);
    const float2 f1 = __half22float2(*(const __half2*)&u.y);
    const float4 xv = *(const float4*)(x + i4);
    float4 o;
    o.x = g * (f0.x - m) + bt + xv.x;
    o.y = g * (f0.y - m) + bt + xv.y;
    o.z = g * (f1.x - m) + bt + xv.z;
    o.w = g * (f1.y - m) + bt + xv.w;
    *(float4*)(out + i4) = o;
}

extern "C" void kernel_launch(void* const* d_in, const int* in_sizes, int n_in,
                              void* d_out, int out_size)
{
    const float* x     = (const float*)d_in[0];
    const float* Wq    = (const float*)d_in[1];
    const float* bq    = (const float*)d_in[2];
    const float* Wk    = (const float*)d_in[3];
    const float* bk    = (const float*)d_in[4];
    const float* Wv    = (const float*)d_in[5];
    const float* bv    = (const float*)d_in[6];
    const float* Wo    = (const float*)d_in[7];
    const float* bo    = (const float*)d_in[8];
    const float* gamma = (const float*)d_in[9];
    const float* beta  = (const float*)d_in[10];
    float* out = (float*)d_out;

    __half *xt, *wq, *wkv, *wo, *qt, *kv, *mt, *pp, *yp;
    float *bkv, *mean, *istd;
    cudaGetSymbolAddress((void**)&xt,  g_xt);
    cudaGetSymbolAddress((void**)&wq,  g_wq);
    cudaGetSymbolAddress((void**)&wkv, g_wkv);
    cudaGetSymbolAddress((void**)&wo,  g_wo);
    cudaGetSymbolAddress((void**)&qt,  g_qt);
    cudaGetSymbolAddress((void**)&kv,  g_kv);
    cudaGetSymbolAddress((void**)&mt,  g_mt);
    cudaGetSymbolAddress((void**)&pp,  g_p);
    cudaGetSymbolAddress((void**)&yp,  g_y);
    cudaGetSymbolAddress((void**)&bkv, g_bkv);
    cudaGetSymbolAddress((void**)&mean, g_mean);
    cudaGetSymbolAddress((void**)&istd, g_istd);

    cudaFuncSetAttribute(wgemm<1, 3>, cudaFuncAttributeMaxDynamicSharedMemorySize, SMEM_B);
    cudaFuncSetAttribute(wgemm<2, 1>, cudaFuncAttributeMaxDynamicSharedMemorySize, SMEM_B);
    cudaFuncSetAttribute(wgemm<0, 1>, cudaFuncAttributeMaxDynamicSharedMemorySize, SMEM_B);
    cudaFuncSetAttribute(wgemm<1, 1>, cudaFuncAttributeMaxDynamicSharedMemorySize, SMEM_B);

    // conversions
    xtrans<<<dim3(Tn / 32, Cn / 32, Bn), 256>>>(x, xt);
    const size_t nw4 = (size_t)Dn * Cn / 4;   // per weight tensor
    wconv4<<<dim3((unsigned)((nw4 + 255) / 256), 4), 256>>>(
        Wk, Wv, Wq, Wo, wkv, wkv + (size_t)Dn * Cn, wq, wo, nw4);
    packbias<<<4, 256>>>(bk, bv, bkv);

    const size_t sTC  = (size_t)Tn * Cn;
    const size_t sTD  = (size_t)Tn * Dn;
    const size_t s2DS = (size_t)2 * Dn * Sn;
    const size_t sDD  = (size_t)Dn * Dn;
    const size_t sCD  = (size_t)Cn * Dn;
    const size_t sCT  = (size_t)Cn * Tn;

    // KV proj + fused pool: [Kp;Vp](2D,S) = pool2(Wkv x + bkv)
    const dim3 gkv(Tn / 128, 2 * Dn / 128, Bn);
    wgemm<1, 3><<<gkv, 256, SMEM_B>>>(wkv, xt, bkv, kv, 2 * Dn, Tn, Cn, 1.f, 0, sTC, s2DS);

    // Q^T(T,D) = xT Wq^T + bq(col)
    const dim3 gq(Dn / 128, Tn / 128, Bn);
    wgemm<2, 1><<<gq, 256, SMEM_B>>>(xt, wq, bq, qt, Tn, Dn, Cn, 1.f, sTC, 0, sTD);

    // Mt(D,D) = Kp Vp^T  (= M^T)
    const dim3 gm(Dn / 128, Dn / 128, Bn);
    wgemm<0, 1><<<gm, 256, SMEM_B>>>(kv, kv + (size_t)Dn * Sn, nullptr, mt,
                                     Dn, Dn, Sn, 1.f, s2DS, s2DS, sDD);

    // P(C,D) = Wo M = Wo Mt^T
    const dim3 gp(Dn / 128, Cn / 128, Bn);
    wgemm<0, 1><<<gp, 256, SMEM_B>>>(wo, mt, nullptr, pp, Cn, Dn, Dn, 1.f, 0, sDD, sCD);

    // y(C,T) = (1/T) P Q + bo
    const dim3 gy(Tn / 128, Cn / 128, Bn);
    wgemm<1, 1><<<gy, 256, SMEM_B>>>(pp, qt, bo, yp, Cn, Tn, Dn, 1.f / (float)Tn,
                                     sCD, sTD, sCT);

    // BatchNorm + residual
    bn_stats<<<Cn, 256>>>(yp, mean, istd);
    const size_t total4 = (size_t)Bn * Cn * Tn / 4;
    bn_apply<<<(unsigned)((total4 + 255) / 256), 256>>>(yp, x, mean, istd, gamma, beta, out);
}